// round 1
// baseline (speedup 1.0000x reference)
#include <cuda_runtime.h>

#define LRELU(v) ((v) >= 0.f ? (v) : 0.01f*(v))

constexpr int B_=8, T_=60, S_=36, H_=4, E_=16, PE_=16, AD_=12, D_=28, TA_=10, C_=32, OH_=16;
constexpr int BH = B_*H_;         // 32
constexpr int SS = S_*S_;         // 1296
constexpr int KEEP = 648;         // floor(S*S*0.5)
constexpr float EPSf = 1e-5f;

// ---------------- device scratch (no allocations allowed) ----------------
__device__ float g_scale[T_], g_shift[T_];
__device__ float g_pe[B_*T_*PE_];
__device__ float g_h[BH*T_*S_*E_];       // (b,h,t,s,e)
__device__ float g_hp[BH*T_*S_*D_];      // (b,h,t,s,d)
__device__ float g_alpha[BH*T_*SS];      // (b,h,t,s,j)
__device__ float g_adj[BH*SS];           // (b,h,s,j)
__device__ float g_bidir[H_*SS];         // (h,s,j)
__device__ float g_sim;
__device__ float g_Hc[BH*S_*T_*C_];      // (b,h,s,t,d)
__device__ float g_beta[BH*S_*T_];       // (b,h,s,t)
__device__ float g_out2[BH*S_*OH_];      // (b,h,s,o)

// block reduce, blockDim must be 512
__device__ __forceinline__ float blk_sum512(float v, float* sm){
  int tid = threadIdx.x;
  __syncthreads();
  sm[tid] = v; __syncthreads();
  #pragma unroll
  for(int s=256; s>0; s>>=1){ if(tid<s) sm[tid]+=sm[tid+s]; __syncthreads(); }
  return sm[0];
}

// ---------------- K0: BatchNorm stats per timestep channel ----------------
__global__ void k_bnstats(const float* __restrict__ x, const float* __restrict__ bn_g,
                          const float* __restrict__ bn_b){
  __shared__ float sm[512];
  int t = blockIdx.x, tid = threadIdx.x;
  float v = 0.f;
  if(tid < B_*S_){ int b = tid/S_, s = tid%S_; v = x[(b*T_+t)*S_+s]; }
  float sum = blk_sum512(v, sm);
  float sq  = blk_sum512(v*v, sm);
  if(tid==0){
    float n = (float)(B_*S_);
    float mu = sum/n;
    float var = sq/n - mu*mu;
    float sc = bn_g[t]*rsqrtf(var+EPSf);
    g_scale[t]=sc; g_shift[t]=bn_b[t]-mu*sc;
  }
}

// ---------------- K1: h init = lrelu(BN(x) * obs_emb) * mask ----------------
__global__ void k_hinit(const float* __restrict__ x, const float* __restrict__ mask,
                        const float* __restrict__ w){
  int idx = blockIdx.x*blockDim.x + threadIdx.x;
  if(idx >= BH*T_*S_*E_) return;
  int e  = idx & 15;
  int s  = (idx>>4)%S_;
  int t  = (idx/(16*S_))%T_;
  int hh = (idx/(16*S_*T_))%H_;
  int b  = idx/(16*S_*T_*H_);
  float xn = x[(b*T_+t)*S_+s]*g_scale[t]+g_shift[t];
  float v = xn * w[s*(E_*H_) + hh*E_ + e];
  v = LRELU(v);
  g_h[idx] = v * mask[(b*T_+t)*S_+s];
}

// ---------------- K2: sinusoidal positional encoding ----------------
__global__ void k_pe(const float* __restrict__ times){
  int idx = blockIdx.x*blockDim.x + threadIdx.x;
  if(idx >= B_*T_*PE_) return;
  int k = idx & 15;
  int t = (idx>>4)%T_;
  int b = idx/(16*T_);
  int i = k>>1;
  float div = expf(-(float)i * 1.1512925464970229f); // ln(10000)/8
  float ang = times[b*T_+t]*div;
  g_pe[idx] = (k&1) ? cosf(ang) : sinf(ang);
}

// ---------------- K3: hp = h @ proj_W.T + proj_b, per (b,h,t) tile ----------------
__global__ void k_hp(const float* __restrict__ W, const float* __restrict__ pb){
  __shared__ float sh_h[S_*E_];   // 576
  __shared__ float sh_w[D_*E_];   // 448
  __shared__ float sh_b[D_];
  int blk = blockIdx.x, tid = threadIdx.x;
  int hbase = blk*S_*E_;
  for(int i=tid;i<S_*E_;i+=blockDim.x) sh_h[i]=g_h[hbase+i];
  for(int i=tid;i<D_*E_;i+=blockDim.x) sh_w[i]=W[i];
  if(tid<D_) sh_b[tid]=pb[tid];
  __syncthreads();
  int pbase = blk*S_*D_;
  for(int o=tid;o<S_*D_;o+=blockDim.x){
    int s=o/D_, d=o%D_;
    float sum = sh_b[d];
    #pragma unroll
    for(int e=0;e<E_;e++) sum += sh_h[s*E_+e]*sh_w[d*E_+e];
    g_hp[pbase+o]=sum;
  }
}

// ---------------- K4: alpha[s,j] = lrelu(hp[s,:12]·aw[j] + hp[s,12:]·pe) ----------------
__global__ void k_alpha(const float* __restrict__ aw){ // (H,S,AD) slice for this layer
  __shared__ float sh_hp[S_*D_];   // 1008
  __shared__ float sh_aw[S_*AD_];  // 432
  __shared__ float sh_pe[PE_];
  __shared__ float sh_C[S_];
  int blk = blockIdx.x, tid = threadIdx.x;
  int bh = blk/T_, t = blk%T_;
  int b = bh/H_, hh = bh%H_;
  int pbase = blk*S_*D_;
  for(int i=tid;i<S_*D_;i+=blockDim.x) sh_hp[i]=g_hp[pbase+i];
  for(int i=tid;i<S_*AD_;i+=blockDim.x) sh_aw[i]=aw[hh*S_*AD_+i];
  if(tid<PE_) sh_pe[tid]=g_pe[(b*T_+t)*PE_+tid];
  __syncthreads();
  if(tid<S_){
    float c=0.f;
    #pragma unroll
    for(int d=0;d<PE_;d++) c += sh_hp[tid*D_+AD_+d]*sh_pe[d];
    sh_C[tid]=c;
  }
  __syncthreads();
  int abase = blk*SS;
  for(int o=tid;o<SS;o+=blockDim.x){
    int s=o/S_, j=o%S_;
    float sum = sh_C[s];
    #pragma unroll
    for(int d=0;d<AD_;d++) sum += sh_hp[s*D_+d]*sh_aw[j*AD_+d];
    g_alpha[abase+o]=LRELU(sum);
  }
}

// ---------------- K5: adj = lrelu(1 * sum_t alpha / cnt)  (layer-1 only, adj_old=1) ----------------
__global__ void k_adj(const float* __restrict__ mask){
  int idx = blockIdx.x*blockDim.x + threadIdx.x;
  if(idx >= BH*SS) return;
  int bh = idx/SS; int b = bh/H_;
  int sj = idx%SS; int s = sj/S_;
  float cnt=0.f;
  for(int t=0;t<T_;t++) cnt += mask[(b*T_+t)*S_+s];
  float asum=0.f;
  for(int t=0;t<T_;t++) asum += g_alpha[(bh*T_+t)*SS+sj];
  float v = asum/cnt;
  g_adj[idx] = LRELU(v);
}

// ---------------- K6: prune — keep top half by stable ascending rank ----------------
__global__ void k_prune(){
  __shared__ float vals[SS];
  int base = blockIdx.x*SS;
  for(int i=threadIdx.x;i<SS;i+=blockDim.x) vals[i]=g_adj[base+i];
  __syncthreads();
  for(int i=threadIdx.x;i<SS;i+=blockDim.x){
    float v = vals[i]; int cnt=0;
    for(int j=0;j<SS;j++){
      float vj = vals[j];
      cnt += (vj<v) || (vj==v && j<i);
    }
    if(cnt<KEEP) g_adj[base+i]=0.f;
  }
}

// ---------------- K7: sim = pair_sim(adj) ----------------
__global__ void k_sim(){
  __shared__ float sm[512];
  int tid = threadIdx.x;
  float sq=0.f, tot2=0.f;
  for(int pos=tid; pos<H_*SS; pos+=512){
    int hh=pos/SS, sj=pos%SS;
    float ts=0.f;
    for(int b=0;b<B_;b++){
      float v = g_adj[(b*H_+hh)*SS+sj];
      sq += v*v; ts += v;
    }
    tot2 += ts*ts;
  }
  float Sq = blk_sum512(sq, sm);
  float T2 = blk_sum512(tot2, sm);
  if(tid==0) g_sim = ((float)B_*Sq - T2) / (float)((B_-1)*(B_-1)) / (float)SS;
}

// ---------------- K8: bidir[h,s,j] = lrelu(bw[h,s]·bw[h,j]) ----------------
__global__ void k_bidir(const float* __restrict__ bw){
  int idx = blockIdx.x*blockDim.x + threadIdx.x;
  if(idx >= H_*SS) return;
  int hh = idx/SS; int s = (idx/S_)%S_; int j = idx%S_;
  float sum=0.f;
  #pragma unroll
  for(int d=0;d<AD_;d++) sum += bw[(hh*S_+s)*AD_+d]*bw[(hh*S_+j)*AD_+d];
  g_bidir[idx]=LRELU(sum);
}

// ---------------- K9: message passing, per (b,h,t) tile, in-place on g_h ----------------
__global__ void k_msg(int use_adj){
  __shared__ float sh_h[S_*E_];   // 576
  __shared__ float sh_w[SS];      // 1296
  int blk = blockIdx.x;
  int bh = blk/T_; int hh = bh%H_;
  int hbase = blk*S_*E_;
  int abase = blk*SS;
  int adjbase = bh*SS;
  for(int i=threadIdx.x;i<S_*E_;i+=blockDim.x) sh_h[i]=g_h[hbase+i];
  for(int o=threadIdx.x;o<SS;o+=blockDim.x){
    float a  = g_alpha[abase+o];
    float bd = g_bidir[hh*SS+o];
    float ad = use_adj ? g_adj[adjbase+o] : 1.f;
    float w = bd*a*ad;
    sh_w[o]=LRELU(w);
  }
  __syncthreads();
  for(int o=threadIdx.x;o<S_*E_;o+=blockDim.x){
    int s=o>>4, e=o&15;
    float sum=0.f;
    #pragma unroll
    for(int j=0;j<S_;j++){
      float p = sh_h[j*E_+e]*sh_w[s*S_+j];
      sum += LRELU(p);
    }
    g_h[hbase+o]=LRELU(sum);
  }
}

// ---------------- K10: Hc build + Q,K + collapsed beta, per (b,h,s) ----------------
__global__ void k_hcqk(const float* __restrict__ Wq, const float* __restrict__ bq,
                       const float* __restrict__ Wk, const float* __restrict__ bk,
                       const float* __restrict__ Ws, const float* __restrict__ bs){
  __shared__ float Hc[T_*C_];   // 1920
  __shared__ float Qs[T_*TA_];  // 600
  __shared__ float Ks[T_*TA_];  // 600
  __shared__ float wq[TA_*C_], wk[TA_*C_];
  __shared__ float bqs[TA_], bks[TA_], wss[T_], kt[TA_];
  int blk = blockIdx.x;
  int bh = blk/S_, s = blk%S_;
  int b = bh/H_;
  int tid = threadIdx.x;
  for(int o=tid;o<T_*C_;o+=blockDim.x){
    int t=o>>5, d=o&31;
    float v = (d<E_) ? g_h[(bh*T_+t)*S_*E_ + s*E_ + d]
                     : g_pe[(b*T_+t)*PE_ + (d-E_)];
    Hc[o]=v;
    g_Hc[blk*T_*C_+o]=v;
  }
  for(int o=tid;o<TA_*C_;o+=blockDim.x){ wq[o]=Wq[o]; wk[o]=Wk[o]; }
  if(tid<TA_){ bqs[tid]=bq[tid]; bks[tid]=bk[tid]; }
  if(tid<T_) wss[tid]=Ws[tid];
  __syncthreads();
  for(int o=tid;o<T_*TA_;o+=blockDim.x){
    int t=o/TA_, q=o%TA_;
    float sq_=bqs[q], sk_=bks[q];
    #pragma unroll
    for(int d=0;d<C_;d++){ float hv=Hc[t*C_+d]; sq_+=hv*wq[q*C_+d]; sk_+=hv*wk[q*C_+d]; }
    Qs[o]=sq_; Ks[o]=sk_;
  }
  __syncthreads();
  if(tid<TA_){
    float sum=0.f;
    #pragma unroll
    for(int u=0;u<T_;u++) sum += wss[u]*Ks[u*TA_+tid];
    kt[tid]=sum;
  }
  __syncthreads();
  if(tid<T_){
    float sum = bs[0];
    #pragma unroll
    for(int q=0;q<TA_;q++) sum += Qs[tid*TA_+q]*kt[q];
    g_beta[blk*T_+tid]=sum;
  }
}

// ---------------- K11: LayerNorm on beta over (S,T) per (b,h) ----------------
__global__ void k_lnt(const float* __restrict__ g, const float* __restrict__ b_){
  __shared__ float sm[512];
  __shared__ float mu_, rs_;
  int bh = blockIdx.x, tid = threadIdx.x;
  int base = bh*S_*T_;
  float s1=0.f, s2=0.f;
  for(int i=tid;i<S_*T_;i+=512){ float v=g_beta[base+i]; s1+=v; s2+=v*v; }
  float sum = blk_sum512(s1, sm);
  float sq  = blk_sum512(s2, sm);
  if(tid==0){ float n=(float)(S_*T_); float mu=sum/n; float var=sq/n-mu*mu; mu_=mu; rs_=rsqrtf(var+EPSf); }
  __syncthreads();
  for(int i=tid;i<S_*T_;i+=512){
    float v = (g_beta[base+i]-mu_)*rs_;
    g_beta[base+i] = v*g[i]+b_[i];   // i = s*T+t matches lnt layout (S,T)
  }
}

// ---------------- K12: out1 = lrelu(beta·Hc), out2 = lrelu(out1 @ Wse.T + bse) ----------------
__global__ void k_out(const float* __restrict__ Wse, const float* __restrict__ bse){
  __shared__ float Hc[T_*C_];
  __shared__ float bet[T_];
  __shared__ float ws[OH_*C_];
  __shared__ float o1[C_];
  int blk = blockIdx.x, tid = threadIdx.x;
  for(int o=tid;o<T_*C_;o+=blockDim.x) Hc[o]=g_Hc[blk*T_*C_+o];
  if(tid<T_) bet[tid]=g_beta[blk*T_+tid];
  for(int o=tid;o<OH_*C_;o+=blockDim.x) ws[o]=Wse[o];
  __syncthreads();
  if(tid<C_){
    float sum=0.f;
    #pragma unroll
    for(int t=0;t<T_;t++) sum += bet[t]*Hc[t*C_+tid];
    o1[tid]=LRELU(sum);
  }
  __syncthreads();
  if(tid<OH_){
    float sum=bse[tid];
    #pragma unroll
    for(int d=0;d<C_;d++) sum += o1[d]*ws[tid*C_+d];
    g_out2[blk*OH_+tid]=LRELU(sum);
  }
}

// ---------------- K13: LayerNorm on out2 over (S,16) per (b,h) + final write ----------------
__global__ void k_ln2(const float* __restrict__ g, const float* __restrict__ b_,
                      float* __restrict__ out, int out_size){
  __shared__ float sm[512];
  __shared__ float mu_, rs_;
  int bh = blockIdx.x, tid = threadIdx.x;
  int b = bh/H_, hh = bh%H_;
  int base = bh*S_*OH_;
  float s1=0.f, s2=0.f;
  for(int i=tid;i<S_*OH_;i+=512){ float v=g_out2[base+i]; s1+=v; s2+=v*v; }
  float sum = blk_sum512(s1, sm);
  float sq  = blk_sum512(s2, sm);
  if(tid==0){ float n=(float)(S_*OH_); float mu=sum/n; float var=sq/n-mu*mu; mu_=mu; rs_=rsqrtf(var+EPSf); }
  __syncthreads();
  for(int i=tid;i<S_*OH_;i+=512){
    int s=i/OH_, o=i%OH_;
    float v = (g_out2[base+i]-mu_)*rs_*g[i]+b_[i];  // lns layout (S,16)
    out[(b*S_+s)*(H_*OH_) + hh*OH_ + o]=v;
  }
  if(bh==0 && tid==0 && out_size > B_*S_*H_*OH_) out[B_*S_*H_*OH_]=g_sim;
}

// ---------------- launcher ----------------
extern "C" void kernel_launch(void* const* d_in, const int* in_sizes, int n_in,
                              void* d_out, int out_size){
  const float* x      = (const float*)d_in[0];
  const float* times  = (const float*)d_in[1];
  const float* mask   = (const float*)d_in[2];
  const float* bn_g   = (const float*)d_in[3];
  const float* bn_b   = (const float*)d_in[4];
  const float* obs    = (const float*)d_in[5];
  const float* attn_w = (const float*)d_in[6];
  const float* bidir_w= (const float*)d_in[7];
  const float* proj_W = (const float*)d_in[8];
  const float* proj_b = (const float*)d_in[9];
  const float* Wq     = (const float*)d_in[10];
  const float* bq     = (const float*)d_in[11];
  const float* Wk     = (const float*)d_in[12];
  const float* bk     = (const float*)d_in[13];
  const float* Ws     = (const float*)d_in[14];
  const float* bs     = (const float*)d_in[15];
  const float* lnt_g  = (const float*)d_in[16];
  const float* lnt_b  = (const float*)d_in[17];
  const float* Wse    = (const float*)d_in[18];
  const float* bse    = (const float*)d_in[19];
  const float* lns_g  = (const float*)d_in[20];
  const float* lns_b  = (const float*)d_in[21];
  float* out = (float*)d_out;

  k_bnstats<<<T_, 512>>>(x, bn_g, bn_b);
  k_hinit<<<(BH*T_*S_*E_+255)/256, 256>>>(x, mask, obs);
  k_pe<<<(B_*T_*PE_+255)/256, 256>>>(times);

  for(int lay=0; lay<2; lay++){
    k_hp<<<BH*T_, 256>>>(proj_W, proj_b);
    k_alpha<<<BH*T_, 256>>>(attn_w + (size_t)lay*H_*S_*AD_);
    if(lay){
      k_adj<<<(BH*SS+255)/256, 256>>>(mask);
      k_prune<<<BH, 512>>>();
      k_sim<<<1, 512>>>();
    }
    k_bidir<<<(H_*SS+255)/256, 256>>>(bidir_w + (size_t)lay*H_*S_*AD_);
    k_msg<<<BH*T_, 512>>>(lay);
  }

  k_hcqk<<<BH*S_, 512>>>(Wq, bq, Wk, bk, Ws, bs);
  k_lnt<<<BH, 512>>>(lnt_g, lnt_b);
  k_out<<<BH*S_, 512>>>(Wse, bse);
  k_ln2<<<BH, 512>>>(lns_g, lns_b, out, out_size);
}